// round 1
// baseline (speedup 1.0000x reference)
#include <cuda_runtime.h>
#include <cstdio>

#define MAXN 50000
#define MAXE 800000
#define DINC 128
#define DHC  128
#define DOUTC 64

// ---- scratch (static device globals; no allocation allowed) ----
__device__ int   g_deg[MAXN];
__device__ float g_dinv[MAXN];
__device__ float g_xw1[MAXN * DHC];
__device__ float g_h1 [MAXN * DHC];
__device__ float g_xw2[MAXN * DOUTC];
__device__ float g_h2 [MAXN * DOUTC];

// ---------------- degree / norm ----------------
__global__ void k_zero_deg(int* deg, int n) {
    int i = blockIdx.x * blockDim.x + threadIdx.x;
    if (i < n) deg[i] = 0;
}
__global__ void k_deg(const int* __restrict__ dst, int* deg, int E) {
    int e = blockIdx.x * blockDim.x + threadIdx.x;
    if (e < E) atomicAdd(&deg[dst[e]], 1);
}
__global__ void k_dinv(const int* __restrict__ deg, float* dinv, int n) {
    int i = blockIdx.x * blockDim.x + threadIdx.x;
    if (i < n) dinv[i] = rsqrtf((float)(deg[i] + 1));  // +1 self-loop
}

// ---------------- GEMM: out[n,NCOL] = act(X[n,128]) @ W[128,NCOL] ----------------
// BLK_ROWS=32 rows per block, 256 threads. K fixed at 128.
template <int NCOL, bool RELU_IN>
__global__ void k_gemm_k128(const float* __restrict__ X, const float* __restrict__ W,
                            float* __restrict__ out, int n) {
    constexpr int KT = 32;
    constexpr int COLV = NCOL / 4;              // float4 columns
    constexpr int RPT = 32 * COLV / 256;        // rows per thread (4 for 128, 2 for 64)
    __shared__ float Xs[32 * KT];
    __shared__ float Ws[KT * NCOL];

    int tid = threadIdx.x;
    int row0 = blockIdx.x * 32;
    int cv = tid % COLV;
    int rg = tid / COLV;

    float4 acc[RPT];
#pragma unroll
    for (int j = 0; j < RPT; j++) acc[j] = make_float4(0.f, 0.f, 0.f, 0.f);

    for (int k0 = 0; k0 < 128; k0 += KT) {
        __syncthreads();
        // stage X tile: 32 rows x 32 k
        {
            int rr = tid / (KT / 4);        // 0..31
            int k4 = (tid % (KT / 4)) * 4;  // 0,4,...,28
            int row = row0 + rr;
            float4 v = make_float4(0.f, 0.f, 0.f, 0.f);
            if (row < n) v = *reinterpret_cast<const float4*>(X + row * 128 + k0 + k4);
            if (RELU_IN) {
                v.x = fmaxf(v.x, 0.f); v.y = fmaxf(v.y, 0.f);
                v.z = fmaxf(v.z, 0.f); v.w = fmaxf(v.w, 0.f);
            }
            *reinterpret_cast<float4*>(Xs + rr * KT + k4) = v;
        }
        // stage W tile: KT x NCOL
#pragma unroll
        for (int i = 0; i < KT * NCOL / 4; i += 256) {
            int lin = tid + i;
            int kk = lin / COLV;
            int c = (lin % COLV) * 4;
            *reinterpret_cast<float4*>(Ws + kk * NCOL + c) =
                *reinterpret_cast<const float4*>(W + (k0 + kk) * NCOL + c);
        }
        __syncthreads();
#pragma unroll
        for (int kk = 0; kk < KT; kk++) {
            float4 w = *reinterpret_cast<float4*>(Ws + kk * NCOL + cv * 4);
#pragma unroll
            for (int j = 0; j < RPT; j++) {
                float xv = Xs[(rg * RPT + j) * KT + kk];
                acc[j].x += xv * w.x; acc[j].y += xv * w.y;
                acc[j].z += xv * w.z; acc[j].w += xv * w.w;
            }
        }
    }
#pragma unroll
    for (int j = 0; j < RPT; j++) {
        int row = row0 + rg * RPT + j;
        if (row < n)
            *reinterpret_cast<float4*>(out + row * NCOL + cv * 4) = acc[j];
    }
}

// ---------------- h init: h[i] = xw[i] * dinv[i]^2 + b   (self-loop + bias) ----------------
template <int VPN>  // float4s per node
__global__ void k_hinit(const float4* __restrict__ xw, const float* __restrict__ dinv,
                        const float4* __restrict__ b, float4* __restrict__ h, int n) {
    int t = blockIdx.x * blockDim.x + threadIdx.x;
    if (t >= n * VPN) return;
    int node = t / VPN;
    int lane = t % VPN;
    float di = dinv[node];
    float s = di * di;
    float4 v = xw[t];
    float4 bb = b[lane];
    h[t] = make_float4(v.x * s + bb.x, v.y * s + bb.y, v.z * s + bb.z, v.w * s + bb.w);
}

// ---------------- scatter: h[d] += xw[s] * dinv[s]*dinv[d] ----------------
template <int VPN>  // float4s per node (32 for d=128, 16 for d=64)
__global__ void k_scatter(const float4* __restrict__ xw, const int* __restrict__ src,
                          const int* __restrict__ dst, const float* __restrict__ dinv,
                          float4* h, int E) {
    int t = blockIdx.x * blockDim.x + threadIdx.x;
    int e = t / VPN;
    int lane = t % VPN;
    if (e >= E) return;
    int s = __ldg(src + e);
    int d = __ldg(dst + e);
    float norm = __ldg(dinv + s) * __ldg(dinv + d);
    float4 v = __ldg(xw + s * VPN + lane);
    float4 m = make_float4(v.x * norm, v.y * norm, v.z * norm, v.w * norm);
    atomicAdd(&h[d * VPN + lane], m);  // sm_90+ vector red.global.add.v4.f32
}

// ---------------- edge scorer: score[e] = dot(h2[s], h2[d]) over 64 dims ----------------
__global__ void k_score(const float4* __restrict__ h2, const int* __restrict__ src,
                        const int* __restrict__ dst, float* __restrict__ out, int E) {
    int t = blockIdx.x * blockDim.x + threadIdx.x;
    int e = t >> 4;
    int lane = t & 15;
    if (e >= E) return;
    int s = __ldg(src + e);
    int d = __ldg(dst + e);
    float4 a = __ldg(h2 + s * 16 + lane);
    float4 b = __ldg(h2 + d * 16 + lane);
    float p = a.x * b.x + a.y * b.y + a.z * b.z + a.w * b.w;
#pragma unroll
    for (int off = 8; off; off >>= 1) p += __shfl_xor_sync(0xFFFFFFFFu, p, off);
    if (lane == 0) out[e] = p;
}

static inline int cdiv(long long a, int b) { return (int)((a + b - 1) / b); }

extern "C" void kernel_launch(void* const* d_in, const int* in_sizes, int n_in,
                              void* d_out, int out_size) {
    const float* x   = (const float*)d_in[0];  // [n,128]
    const int*   src = (const int*)  d_in[1];  // [E]
    const int*   dst = (const int*)  d_in[2];  // [E]
    const float* W1  = (const float*)d_in[3];  // [128,128]
    const float* b1  = (const float*)d_in[4];  // [128]
    const float* W2  = (const float*)d_in[5];  // [128,64]
    const float* b2  = (const float*)d_in[6];  // [64]
    float* score = (float*)d_out;

    int n = in_sizes[0] / DINC;
    int E = in_sizes[1];

    void *p_deg, *p_dinv, *p_xw1, *p_h1, *p_xw2, *p_h2;
    cudaGetSymbolAddress(&p_deg,  g_deg);
    cudaGetSymbolAddress(&p_dinv, g_dinv);
    cudaGetSymbolAddress(&p_xw1,  g_xw1);
    cudaGetSymbolAddress(&p_h1,   g_h1);
    cudaGetSymbolAddress(&p_xw2,  g_xw2);
    cudaGetSymbolAddress(&p_h2,   g_h2);
    int*   deg  = (int*)p_deg;
    float* dinv = (float*)p_dinv;
    float* xw1  = (float*)p_xw1;
    float* h1   = (float*)p_h1;
    float* xw2  = (float*)p_xw2;
    float* h2   = (float*)p_h2;

    const int B = 256;

    // degrees + normalization
    k_zero_deg<<<cdiv(n, B), B>>>(deg, n);
    k_deg<<<cdiv(E, B), B>>>(dst, deg, E);
    k_dinv<<<cdiv(n, B), B>>>(deg, dinv, n);

    // layer 1: xw1 = X @ W1
    k_gemm_k128<DHC, false><<<cdiv(n, 32), B>>>(x, W1, xw1, n);
    // h1 = self-loop + bias init, then scatter edges
    k_hinit<32><<<cdiv((long long)n * 32, B), B>>>((const float4*)xw1, dinv,
                                                   (const float4*)b1, (float4*)h1, n);
    k_scatter<32><<<cdiv((long long)E * 32, B), B>>>((const float4*)xw1, src, dst, dinv,
                                                     (float4*)h1, E);

    // layer 2: xw2 = relu(h1) @ W2
    k_gemm_k128<DOUTC, true><<<cdiv(n, 32), B>>>(h1, W2, xw2, n);
    k_hinit<16><<<cdiv((long long)n * 16, B), B>>>((const float4*)xw2, dinv,
                                                   (const float4*)b2, (float4*)h2, n);
    k_scatter<16><<<cdiv((long long)E * 16, B), B>>>((const float4*)xw2, src, dst, dinv,
                                                     (float4*)h2, E);

    // edge scores
    k_score<<<cdiv((long long)E * 16, B), B>>>((const float4*)h2, src, dst, score, E);
}

// round 3
// speedup vs baseline: 1.1740x; 1.1740x over previous
#include <cuda_runtime.h>

#define MAXN 50000
#define MAXE 800000
#define DINC 128
#define DHC  128
#define DOUTC 64

// ---- scratch (static device globals; no allocation allowed) ----
__device__ int   g_deg[MAXN];
__device__ float g_dinv[MAXN];
__device__ int   g_offs[MAXN + 1];
__device__ int   g_cursor[MAXN];
__device__ int   g_bsrc[MAXE];
__device__ float g_xw1[MAXN * DHC];
__device__ float g_h1 [MAXN * DHC];
__device__ float g_xw2[MAXN * DOUTC];
__device__ float g_h2 [MAXN * DOUTC];

// ---------------- small helpers ----------------
__device__ __forceinline__ float4 f4fma(float4 a, float s, float4 acc) {
    acc.x += a.x * s; acc.y += a.y * s; acc.z += a.z * s; acc.w += a.w * s;
    return acc;
}

// ---------------- degree / norm ----------------
__global__ void k_deg(const int* __restrict__ dst, int* deg, int E) {
    int e = blockIdx.x * blockDim.x + threadIdx.x;
    if (e < E) atomicAdd(&deg[dst[e]], 1);
}
__global__ void k_dinv(const int* __restrict__ deg, float* dinv, int n) {
    int i = blockIdx.x * blockDim.x + threadIdx.x;
    if (i < n) dinv[i] = rsqrtf((float)(deg[i] + 1));  // +1 self-loop
}

// ---------------- single-block exclusive scan over deg -> offs[0..n] ----------------
__global__ void k_scan(const int* __restrict__ deg, int* __restrict__ offs, int n) {
    const int T = 1024;
    __shared__ int s[T];
    int tid = threadIdx.x;
    int per = (n + T - 1) / T;
    int start = tid * per;
    int sum = 0;
    for (int i = 0; i < per; i++) {
        int idx = start + i;
        if (idx < n) sum += deg[idx];
    }
    s[tid] = sum;
    __syncthreads();
    // inclusive block scan
    for (int d = 1; d < T; d <<= 1) {
        int v = 0;
        if (tid >= d) v = s[tid - d];
        __syncthreads();
        if (tid >= d) s[tid] += v;
        __syncthreads();
    }
    int run = s[tid] - sum;  // exclusive prefix of this chunk
    for (int i = 0; i < per; i++) {
        int idx = start + i;
        if (idx < n) {
            offs[idx] = run;
            run += deg[idx];
        }
    }
    if (tid == T - 1) offs[n] = run;  // total = E
}

// ---------------- bucket edges by dst ----------------
__global__ void k_bucket(const int* __restrict__ src, const int* __restrict__ dst,
                         int* cursor, int* __restrict__ bsrc, int E) {
    int e = blockIdx.x * blockDim.x + threadIdx.x;
    if (e >= E) return;
    int d = dst[e];
    int p = atomicAdd(&cursor[d], 1);
    bsrc[p] = src[e];
}

// ---------------- GEMM: out[n,NCOL] = act(X[n,128]) @ W[128,NCOL] ----------------
// 64-row tile, 256 threads, KT=16, transposed X staging.
template <int NCOL, bool RELU_IN>
__global__ __launch_bounds__(256) void k_gemm(const float* __restrict__ X,
                                              const float* __restrict__ W,
                                              float* __restrict__ out, int n) {
    constexpr int KT = 16;
    constexpr int COLG = NCOL / 4;     // float4 col groups: 32 or 16
    constexpr int RTH = 256 / COLG;    // row-thread groups: 8 or 16
    constexpr int RPT = 64 / RTH;      // rows per thread: 8 or 4
    __shared__ float Xs[KT][68];       // [k][row], padded (68*4=272B, 16B-aligned rows)
    __shared__ float Ws[KT][NCOL];

    int tid = threadIdx.x;
    int row0 = blockIdx.x * 64;
    int cx = tid % COLG;
    int ry = tid / COLG;

    float4 acc[RPT];
#pragma unroll
    for (int j = 0; j < RPT; j++) acc[j] = make_float4(0.f, 0.f, 0.f, 0.f);

    for (int k0 = 0; k0 < 128; k0 += KT) {
        __syncthreads();
        // stage X (transposed): 64 rows x 16 k = 256 float4 loads
        {
            int rr = tid >> 2;              // 0..63
            int kv = (tid & 3) * 4;         // 0,4,8,12
            int row = row0 + rr;
            float4 v = make_float4(0.f, 0.f, 0.f, 0.f);
            if (row < n) v = __ldg(reinterpret_cast<const float4*>(X + row * 128 + k0 + kv));
            if (RELU_IN) {
                v.x = fmaxf(v.x, 0.f); v.y = fmaxf(v.y, 0.f);
                v.z = fmaxf(v.z, 0.f); v.w = fmaxf(v.w, 0.f);
            }
            Xs[kv + 0][rr] = v.x; Xs[kv + 1][rr] = v.y;
            Xs[kv + 2][rr] = v.z; Xs[kv + 3][rr] = v.w;
        }
        // stage W: KT x NCOL
#pragma unroll
        for (int lin = tid; lin < KT * COLG; lin += 256) {
            int kk = lin / COLG;
            int c = lin % COLG;
            *reinterpret_cast<float4*>(&Ws[kk][c * 4]) =
                __ldg(reinterpret_cast<const float4*>(W + (k0 + kk) * NCOL + c * 4));
        }
        __syncthreads();
#pragma unroll
        for (int kk = 0; kk < KT; kk++) {
            float4 w = *reinterpret_cast<float4*>(&Ws[kk][cx * 4]);
#pragma unroll
            for (int rv = 0; rv < RPT / 4; rv++) {
                float4 xr = *reinterpret_cast<float4*>(&Xs[kk][ry * RPT + rv * 4]);
                acc[rv * 4 + 0] = f4fma(w, xr.x, acc[rv * 4 + 0]);
                acc[rv * 4 + 1] = f4fma(w, xr.y, acc[rv * 4 + 1]);
                acc[rv * 4 + 2] = f4fma(w, xr.z, acc[rv * 4 + 2]);
                acc[rv * 4 + 3] = f4fma(w, xr.w, acc[rv * 4 + 3]);
            }
        }
    }
#pragma unroll
    for (int j = 0; j < RPT; j++) {
        int row = row0 + ry * RPT + j;
        if (row < n)
            *reinterpret_cast<float4*>(out + row * NCOL + cx * 4) = acc[j];
    }
}

// ---------------- gather aggregation, d=128: warp per node, lane = float4 col ----------------
__global__ __launch_bounds__(256) void k_agg128(
    const float4* __restrict__ xw, const int* __restrict__ offs,
    const int* __restrict__ bsrc, const float* __restrict__ dinv,
    const float4* __restrict__ bias, float4* __restrict__ h, int n) {
    int t = blockIdx.x * blockDim.x + threadIdx.x;
    int node = t >> 5;
    int lane = t & 31;
    if (node >= n) return;
    float dn = __ldg(dinv + node);
    float4 bb = __ldg(bias + lane);
    float4 acc = f4fma(__ldg(xw + (size_t)node * 32 + lane), dn * dn, bb);
    int beg = __ldg(offs + node), end = __ldg(offs + node + 1);
    int j = beg;
    for (; j + 1 < end; j += 2) {
        int s0 = __ldg(bsrc + j), s1 = __ldg(bsrc + j + 1);
        float n0 = __ldg(dinv + s0) * dn, n1 = __ldg(dinv + s1) * dn;
        float4 v0 = __ldg(xw + (size_t)s0 * 32 + lane);
        float4 v1 = __ldg(xw + (size_t)s1 * 32 + lane);
        acc = f4fma(v0, n0, acc);
        acc = f4fma(v1, n1, acc);
    }
    if (j < end) {
        int s0 = __ldg(bsrc + j);
        acc = f4fma(__ldg(xw + (size_t)s0 * 32 + lane), __ldg(dinv + s0) * dn, acc);
    }
    h[(size_t)node * 32 + lane] = acc;
}

// ---------------- gather aggregation, d=64: warp per node, lane = float2 col ----------------
__global__ __launch_bounds__(256) void k_agg64(
    const float2* __restrict__ xw, const int* __restrict__ offs,
    const int* __restrict__ bsrc, const float* __restrict__ dinv,
    const float2* __restrict__ bias, float2* __restrict__ h, int n) {
    int t = blockIdx.x * blockDim.x + threadIdx.x;
    int node = t >> 5;
    int lane = t & 31;
    if (node >= n) return;
    float dn = __ldg(dinv + node);
    float2 bb = __ldg(bias + lane);
    float2 v0 = __ldg(xw + (size_t)node * 32 + lane);
    float s = dn * dn;
    float2 acc = make_float2(v0.x * s + bb.x, v0.y * s + bb.y);
    int beg = __ldg(offs + node), end = __ldg(offs + node + 1);
    int j = beg;
    for (; j + 1 < end; j += 2) {
        int s0 = __ldg(bsrc + j), s1 = __ldg(bsrc + j + 1);
        float n0 = __ldg(dinv + s0) * dn, n1 = __ldg(dinv + s1) * dn;
        float2 a = __ldg(xw + (size_t)s0 * 32 + lane);
        float2 b = __ldg(xw + (size_t)s1 * 32 + lane);
        acc.x += a.x * n0 + b.x * n1;
        acc.y += a.y * n0 + b.y * n1;
    }
    if (j < end) {
        int s0 = __ldg(bsrc + j);
        float n0 = __ldg(dinv + s0) * dn;
        float2 a = __ldg(xw + (size_t)s0 * 32 + lane);
        acc.x += a.x * n0; acc.y += a.y * n0;
    }
    h[(size_t)node * 32 + lane] = acc;
}

// ---------------- edge scorer: score[e] = dot(h2[s], h2[d]) over 64 dims ----------------
__global__ __launch_bounds__(256) void k_score(const float4* __restrict__ h2,
                                               const int* __restrict__ src,
                                               const int* __restrict__ dst,
                                               float* __restrict__ out, int E) {
    int t = blockIdx.x * blockDim.x + threadIdx.x;
    int e = t >> 4;
    int lane = t & 15;
    if (e >= E) return;
    int s = __ldg(src + e);
    int d = __ldg(dst + e);
    float4 a = __ldg(h2 + (size_t)s * 16 + lane);
    float4 b = __ldg(h2 + (size_t)d * 16 + lane);
    float p = a.x * b.x + a.y * b.y + a.z * b.z + a.w * b.w;
#pragma unroll
    for (int off = 8; off; off >>= 1) p += __shfl_xor_sync(0xFFFFFFFFu, p, off);
    if (lane == 0) out[e] = p;
}

static inline int cdiv(long long a, int b) { return (int)((a + b - 1) / b); }

extern "C" void kernel_launch(void* const* d_in, const int* in_sizes, int n_in,
                              void* d_out, int out_size) {
    const float* x   = (const float*)d_in[0];
    const int*   src = (const int*)  d_in[1];
    const int*   dst = (const int*)  d_in[2];
    const float* W1  = (const float*)d_in[3];
    const float* b1  = (const float*)d_in[4];
    const float* W2  = (const float*)d_in[5];
    const float* b2  = (const float*)d_in[6];
    float* score = (float*)d_out;

    int n = in_sizes[0] / DINC;
    int E = in_sizes[1];

    void *p_deg, *p_dinv, *p_offs, *p_cursor, *p_bsrc, *p_xw1, *p_h1, *p_xw2, *p_h2;
    cudaGetSymbolAddress(&p_deg,    g_deg);
    cudaGetSymbolAddress(&p_dinv,   g_dinv);
    cudaGetSymbolAddress(&p_offs,   g_offs);
    cudaGetSymbolAddress(&p_cursor, g_cursor);
    cudaGetSymbolAddress(&p_bsrc,   g_bsrc);
    cudaGetSymbolAddress(&p_xw1,    g_xw1);
    cudaGetSymbolAddress(&p_h1,     g_h1);
    cudaGetSymbolAddress(&p_xw2,    g_xw2);
    cudaGetSymbolAddress(&p_h2,     g_h2);
    int*   deg    = (int*)p_deg;
    float* dinv   = (float*)p_dinv;
    int*   offs   = (int*)p_offs;
    int*   cursor = (int*)p_cursor;
    int*   bsrc   = (int*)p_bsrc;
    float* xw1    = (float*)p_xw1;
    float* h1     = (float*)p_h1;
    float* xw2    = (float*)p_xw2;
    float* h2     = (float*)p_h2;

    const int B = 256;

    // ---- CSR build (once; reused for both layers) ----
    cudaMemsetAsync(deg, 0, (size_t)n * sizeof(int));
    k_deg<<<cdiv(E, B), B>>>(dst, deg, E);
    k_dinv<<<cdiv(n, B), B>>>(deg, dinv, n);
    k_scan<<<1, 1024>>>(deg, offs, n);
    cudaMemcpyAsync(cursor, offs, (size_t)n * sizeof(int), cudaMemcpyDeviceToDevice);
    k_bucket<<<cdiv(E, B), B>>>(src, dst, cursor, bsrc, E);

    // ---- layer 1 ----
    k_gemm<DHC, false><<<cdiv(n, 64), B>>>(x, W1, xw1, n);
    k_agg128<<<cdiv((long long)n * 32, B), B>>>((const float4*)xw1, offs, bsrc, dinv,
                                                (const float4*)b1, (float4*)h1, n);

    // ---- layer 2 (relu fused into GEMM input) ----
    k_gemm<DOUTC, true><<<cdiv(n, 64), B>>>(h1, W2, xw2, n);
    k_agg64<<<cdiv((long long)n * 32, B), B>>>((const float2*)xw2, offs, bsrc, dinv,
                                               (const float2*)b2, (float2*)h2, n);

    // ---- edge scores ----
    k_score<<<cdiv((long long)E * 16, B), B>>>((const float4*)h2, src, dst, score, E);
}